// round 4
// baseline (speedup 1.0000x reference)
#include <cuda_runtime.h>

// PlanarQuantMSE, single fused kernel, fat-LUT quantizer.
// Per-row normalize, rotate pairs, quantize to nearest of 16 SORTED centroids,
// inverse-rotate, rescale. Output: [x_hat | indices-as-float] concatenated.
//
// Quantizer: cell(v) via FP-magic round; LUT entry {mid_L, c_L, c_{L+1}, L}
// where L = #{midpoints in cells < cell}. idx = L + (v > mid_L). Exact unless
// a cell holds >=2 midpoints (per-block flag -> 15-compare fallback).

#define ROWS 4096
#define DIM  4096
#define TPB  256
#define VPT  4        // float4s per thread (TPB*4*VPT == DIM)
#define NCELL 1024
#define SCALEF 455.0f
// magic = 2^23*1.5 + 512 ; cell = bits(fma(v,S,magic)) - 0x4B400000 = round(v*S)+512
#define MAGICF 12583424.0f
#define BITBASE 0x4B400000

__global__ __launch_bounds__(TPB, 6)
void pq_kernel(const float* __restrict__ x,
               const float* __restrict__ cent,
               const float* __restrict__ rot2,
               float* __restrict__ xhat,
               float* __restrict__ idxout)
{
    __shared__ float4 lut_sh[NCELL];          // {mid_L, c_L, c_{L+1}, (float)L}
    __shared__ float  mid_sh[16];
    __shared__ float  c_sh[16];
    __shared__ int    tc_sh[15];
    __shared__ float  red[TPB / 32];
    __shared__ float  norm_sh;
    __shared__ int    flag_sh;

    const int row = blockIdx.x;
    const int t   = threadIdx.x;

    // ---- issue x loads first so DRAM streams while we do table setup ----
    const float4* xr = (const float4*)(x + (size_t)row * DIM);
    float4 v[VPT];
#pragma unroll
    for (int k = 0; k < VPT; k++) v[k] = __ldcs(&xr[t + k * TPB]);

    // ---- warp-0 setup: centroids, midpoints, cell ids, dup flag ----
    if (t < 16) {
        float cv = __ldg(&cent[t]);
        c_sh[t] = cv;
        float cn = __shfl_down_sync(0x0000ffffu, cv, 1);
        float mm = 0.5f * (cv + cn);
        int cell = __float_as_int(fmaf(mm, SCALEF, MAGICF)) - BITBASE;
        if (t < 15) { mid_sh[t] = mm; tc_sh[t] = cell; }
        else        { mid_sh[15] = 3.0e38f; }
        int celln = __shfl_down_sync(0x0000ffffu, cell, 1);
        unsigned dup = __ballot_sync(0x0000ffffu, (t < 14) && (cell == celln));
        if (t == 0) flag_sh = (dup != 0u) ? 1 : 0;
    }

    // ---- row sum of squares ----
    float ss = 0.0f;
#pragma unroll
    for (int k = 0; k < VPT; k++)
        ss += v[k].x * v[k].x + v[k].y * v[k].y
            + v[k].z * v[k].z + v[k].w * v[k].w;
#pragma unroll
    for (int o = 16; o > 0; o >>= 1)
        ss += __shfl_xor_sync(0xffffffffu, ss, o);
    if ((t & 31) == 0) red[t >> 5] = ss;
    __syncthreads();                                   // barrier A

    // ---- fat-LUT build: 4 entries/thread, tc via broadcast LDS (low regs) ----
    {
        const int base = t * 4;
        int L0 = 0, L1 = 0, L2 = 0, L3 = 0;
#pragma unroll
        for (int j = 0; j < 15; j++) {
            int cj = tc_sh[j];
            L0 += (cj < base)     ? 1 : 0;
            L1 += (cj < base + 1) ? 1 : 0;
            L2 += (cj < base + 2) ? 1 : 0;
            L3 += (cj < base + 3) ? 1 : 0;
        }
#pragma unroll
        for (int e = 0; e < 4; e++) {
            int L = (e == 0) ? L0 : (e == 1) ? L1 : (e == 2) ? L2 : L3;
            float4 ent;
            ent.x = mid_sh[L];
            ent.y = c_sh[L];
            ent.z = c_sh[min(L + 1, 15)];
            ent.w = (float)L;
            lut_sh[base + e] = ent;
        }
    }

    if (t < (TPB / 32)) {
        float s2 = red[t];
#pragma unroll
        for (int o = (TPB / 64); o > 0; o >>= 1)
            s2 += __shfl_xor_sync((1u << (TPB / 32)) - 1u, s2, o);
        if (t == 0) norm_sh = fmaxf(sqrtf(s2), 1e-8f);
    }
    __syncthreads();                                   // barrier B

    const float norm = norm_sh;
    const float inv  = 1.0f / norm;
    const int   flag = flag_sh;

    const float4* rr = (const float4*)rot2;            // (c,s,c,s) per float4
    float4* xo = (float4*)(xhat  + (size_t)row * DIM);
    float4* io = (float4*)(idxout + (size_t)row * DIM);

#pragma unroll
    for (int k = 0; k < VPT; k++) {
        const int j = t + k * TPB;
        const float4 rs = __ldg(&rr[j]);

        const float v0 = v[k].x * inv, v1 = v[k].y * inv;
        const float v2 = v[k].z * inv, v3 = v[k].w * inv;

        float r[4];
        r[0] = rs.x * v0 - rs.y * v1;
        r[1] = rs.y * v0 + rs.x * v1;
        r[2] = rs.z * v2 - rs.w * v3;
        r[3] = rs.w * v2 + rs.z * v3;

        float q[4], f[4];
        if (!flag) {
#pragma unroll
            for (int e = 0; e < 4; e++) {
                int cell = __float_as_int(fmaf(r[e], SCALEF, MAGICF)) - BITBASE;
                cell = min(max(cell, 0), NCELL - 1);
                float4 ent = lut_sh[cell];
                bool gt = r[e] > ent.x;                // strict >: argmin tie->low idx
                q[e] = gt ? ent.z : ent.y;
                f[e] = ent.w + (gt ? 1.0f : 0.0f);
            }
        } else {
#pragma unroll
            for (int e = 0; e < 4; e++) {
                int idx = 0;
#pragma unroll
                for (int jj = 0; jj < 15; jj++) idx += (r[e] > mid_sh[jj]) ? 1 : 0;
                q[e] = c_sh[idx];
                f[e] = (float)idx;
            }
        }

        float4 out;
        out.x = (rs.x * q[0] + rs.y * q[1]) * norm;
        out.y = (rs.x * q[1] - rs.y * q[0]) * norm;
        out.z = (rs.z * q[2] + rs.w * q[3]) * norm;
        out.w = (rs.z * q[3] - rs.w * q[2]) * norm;
        __stcs(&xo[j], out);

        float4 fo;
        fo.x = f[0]; fo.y = f[1]; fo.z = f[2]; fo.w = f[3];
        __stcs(&io[j], fo);
    }
}

extern "C" void kernel_launch(void* const* d_in, const int* in_sizes, int n_in,
                              void* d_out, int out_size) {
    const float* x = nullptr;
    const float* cent = nullptr;
    const float* rot2 = nullptr;
    for (int i = 0; i < n_in; i++) {
        if (in_sizes[i] == ROWS * DIM) x    = (const float*)d_in[i];
        else if (in_sizes[i] == 16)    cent = (const float*)d_in[i];
        else if (in_sizes[i] == 4096)  rot2 = (const float*)d_in[i];
    }

    float* xhat = (float*)d_out;
    float* idxf = xhat + (long long)ROWS * DIM;

    pq_kernel<<<ROWS, TPB>>>(x, cent, rot2, xhat, idxf);
}

// round 5
// speedup vs baseline: 1.2168x; 1.2168x over previous
#include <cuda_runtime.h>

// PlanarQuantMSE, single fused kernel.
// Skinny dual-array LUT quantizer: lutL[cell] (byte, L = #midpoints below cell)
// and lutM[cell] (float, mid_L) loaded in PARALLEL from the same index, one
// correction compare, then q = c_sh[idx]. Exact unless a cell holds >= 2
// midpoints (per-block flag -> 15-compare fallback).
// Output: [x_hat | indices-as-float] concatenated.

#define ROWS 4096
#define DIM  4096
#define TPB  256
#define VPT  4        // float4s per thread (TPB*4*VPT == DIM)
#define NCELL 1024
#define SCALEF 455.0f
// magic = 2^23*1.5 + 512 ; cell = bits(fma(v,S,magic)) - 0x4B400000 = round(v*S)+512
#define MAGICF 12583424.0f
#define BITBASE 0x4B400000

__global__ __launch_bounds__(TPB, 6)
void pq_kernel(const float* __restrict__ x,
               const float* __restrict__ cent,
               const float* __restrict__ rot2,
               float* __restrict__ xhat,
               float* __restrict__ idxout)
{
    __shared__ unsigned char lutL_sh[NCELL];   // L per cell
    __shared__ float         lutM_sh[NCELL];   // mid_L per cell
    __shared__ float  mid_sh[16];
    __shared__ float  c_sh[16];
    __shared__ int    tc_sh[15];
    __shared__ float  red[TPB / 32];
    __shared__ float  norm_sh;
    __shared__ int    flag_sh;

    const int row = blockIdx.x;
    const int t   = threadIdx.x;

    // ---- issue x loads first so DRAM streams while we do table setup ----
    const float4* xr = (const float4*)(x + (size_t)row * DIM);
    float4 v[VPT];
#pragma unroll
    for (int k = 0; k < VPT; k++) v[k] = __ldcs(&xr[t + k * TPB]);

    // ---- warp-0 setup: centroids, midpoints, cell ids, dup flag ----
    if (t < 16) {
        float cv = __ldg(&cent[t]);
        c_sh[t] = cv;
        float cn = __shfl_down_sync(0x0000ffffu, cv, 1);
        float mm = 0.5f * (cv + cn);
        int cell = __float_as_int(fmaf(mm, SCALEF, MAGICF)) - BITBASE;
        if (t < 15) { mid_sh[t] = mm; tc_sh[t] = cell; }
        else        { mid_sh[15] = 3.0e38f; }
        int celln = __shfl_down_sync(0x0000ffffu, cell, 1);
        unsigned dup = __ballot_sync(0x0000ffffu, (t < 14) && (cell == celln));
        if (t == 0) flag_sh = (dup != 0u) ? 1 : 0;
    }

    // ---- row sum of squares ----
    float ss = 0.0f;
#pragma unroll
    for (int k = 0; k < VPT; k++)
        ss += v[k].x * v[k].x + v[k].y * v[k].y
            + v[k].z * v[k].z + v[k].w * v[k].w;
#pragma unroll
    for (int o = 16; o > 0; o >>= 1)
        ss += __shfl_xor_sync(0xffffffffu, ss, o);
    if ((t & 31) == 0) red[t >> 5] = ss;
    __syncthreads();                                   // barrier A

    // ---- LUT build: 4 cells/thread; tc via broadcast LDS (keeps regs low) ----
    {
        const int base = t * 4;
        int L0 = 0, L1 = 0, L2 = 0, L3 = 0;
#pragma unroll
        for (int j = 0; j < 15; j++) {
            int cj = tc_sh[j];
            L0 += (cj < base)     ? 1 : 0;
            L1 += (cj < base + 1) ? 1 : 0;
            L2 += (cj < base + 2) ? 1 : 0;
            L3 += (cj < base + 3) ? 1 : 0;
        }
        ((unsigned int*)lutL_sh)[t] =
            (unsigned)L0 | ((unsigned)L1 << 8) | ((unsigned)L2 << 16) | ((unsigned)L3 << 24);
        lutM_sh[base]     = mid_sh[L0];
        lutM_sh[base + 1] = mid_sh[L1];
        lutM_sh[base + 2] = mid_sh[L2];
        lutM_sh[base + 3] = mid_sh[L3];
    }

    if (t < (TPB / 32)) {
        float s2 = red[t];
#pragma unroll
        for (int o = (TPB / 64); o > 0; o >>= 1)
            s2 += __shfl_xor_sync((1u << (TPB / 32)) - 1u, s2, o);
        if (t == 0) norm_sh = fmaxf(sqrtf(s2), 1e-8f);
    }
    __syncthreads();                                   // barrier B

    const float norm = norm_sh;
    const float inv  = 1.0f / norm;
    const int   flag = flag_sh;

    const float4* rr = (const float4*)rot2;            // (c,s,c,s) per float4
    float4* xo = (float4*)(xhat  + (size_t)row * DIM);
    float4* io = (float4*)(idxout + (size_t)row * DIM);

#pragma unroll
    for (int k = 0; k < VPT; k++) {
        const int j = t + k * TPB;
        const float4 rs = __ldg(&rr[j]);

        const float v0 = v[k].x * inv, v1 = v[k].y * inv;
        const float v2 = v[k].z * inv, v3 = v[k].w * inv;

        float r[4];
        r[0] = rs.x * v0 - rs.y * v1;
        r[1] = rs.y * v0 + rs.x * v1;
        r[2] = rs.z * v2 - rs.w * v3;
        r[3] = rs.w * v2 + rs.z * v3;

        float q[4], f[4];
        if (!flag) {
            int cell[4];
#pragma unroll
            for (int e = 0; e < 4; e++) {
                int cc = __float_as_int(fmaf(r[e], SCALEF, MAGICF)) - BITBASE;
                cell[e] = min(max(cc, 0), NCELL - 1);
            }
#pragma unroll
            for (int e = 0; e < 4; e++) {
                float midL = lutM_sh[cell[e]];          // parallel with lutL load
                int   L    = (int)lutL_sh[cell[e]];
                int   idx  = L + ((r[e] > midL) ? 1 : 0);  // strict >: argmin ties->low
                q[e] = c_sh[idx];
                f[e] = (float)idx;
            }
        } else {
#pragma unroll
            for (int e = 0; e < 4; e++) {
                int idx = 0;
#pragma unroll
                for (int jj = 0; jj < 15; jj++) idx += (r[e] > mid_sh[jj]) ? 1 : 0;
                q[e] = c_sh[idx];
                f[e] = (float)idx;
            }
        }

        float4 out;
        out.x = (rs.x * q[0] + rs.y * q[1]) * norm;
        out.y = (rs.x * q[1] - rs.y * q[0]) * norm;
        out.z = (rs.z * q[2] + rs.w * q[3]) * norm;
        out.w = (rs.z * q[3] - rs.w * q[2]) * norm;
        __stcs(&xo[j], out);

        float4 fo;
        fo.x = f[0]; fo.y = f[1]; fo.z = f[2]; fo.w = f[3];
        __stcs(&io[j], fo);
    }
}

extern "C" void kernel_launch(void* const* d_in, const int* in_sizes, int n_in,
                              void* d_out, int out_size) {
    const float* x = nullptr;
    const float* cent = nullptr;
    const float* rot2 = nullptr;
    for (int i = 0; i < n_in; i++) {
        if (in_sizes[i] == ROWS * DIM) x    = (const float*)d_in[i];
        else if (in_sizes[i] == 16)    cent = (const float*)d_in[i];
        else if (in_sizes[i] == 4096)  rot2 = (const float*)d_in[i];
    }

    float* xhat = (float*)d_out;
    float* idxf = xhat + (long long)ROWS * DIM;

    pq_kernel<<<ROWS, TPB>>>(x, cent, rot2, xhat, idxf);
}

// round 6
// speedup vs baseline: 1.2179x; 1.0009x over previous
#include <cuda_runtime.h>

// PlanarQuantMSE, single fused kernel, two-pass-over-L1 variant.
// Pass 1: stream row x through L1 (caching loads), reduce sum-of-squares.
// Pass 2: re-read x from L1 (guaranteed resident: 8 CTAs x 16KB < L1D),
// rotate pairs, quantize via skinny dual LUT (lutL byte + lutM f32, parallel
// loads, 1 correction compare; exact unless a cell holds >=2 midpoints ->
// per-block flag -> 15-compare fallback), inverse-rotate, rescale.
// Output: [x_hat | indices-as-float] concatenated.

#define ROWS 4096
#define DIM  4096
#define TPB  256
#define VPT  4        // float4s per thread (TPB*4*VPT == DIM)
#define NCELL 1024
#define SCALEF 455.0f
// magic = 2^23*1.5 + 512 ; cell = bits(fma(v,S,magic)) - 0x4B400000 = round(v*S)+512
// |r| <= 1 (rotated unit-subvector pair) => cell in [57, 967]: no clamp needed.
#define MAGICF 12583424.0f
#define BITBASE 0x4B400000

__global__ __launch_bounds__(TPB, 8)
void pq_kernel(const float* __restrict__ x,
               const float* __restrict__ cent,
               const float* __restrict__ rot2,
               float* __restrict__ xhat,
               float* __restrict__ idxout)
{
    __shared__ unsigned char lutL_sh[NCELL];   // L per cell
    __shared__ float         lutM_sh[NCELL];   // mid_L per cell
    __shared__ float  mid_sh[16];
    __shared__ float  c_sh[16];
    __shared__ int    tc_sh[15];
    __shared__ float  red[TPB / 32];
    __shared__ float  norm_sh;
    __shared__ int    flag_sh;

    const int row = blockIdx.x;
    const int t   = threadIdx.x;

    const float4* xr = (const float4*)(x + (size_t)row * DIM);

    // ---- pass 1: sum of squares (caching loads fill L1; nothing retained) ----
    float ss = 0.0f;
#pragma unroll
    for (int k = 0; k < VPT; k++) {
        float4 xv = xr[t + k * TPB];
        ss += xv.x * xv.x + xv.y * xv.y + xv.z * xv.z + xv.w * xv.w;
    }

    // ---- warp-0 setup: centroids, midpoints, cell ids, dup flag ----
    if (t < 16) {
        float cv = __ldg(&cent[t]);
        c_sh[t] = cv;
        float cn = __shfl_down_sync(0x0000ffffu, cv, 1);
        float mm = 0.5f * (cv + cn);
        int cell = __float_as_int(fmaf(mm, SCALEF, MAGICF)) - BITBASE;
        if (t < 15) { mid_sh[t] = mm; tc_sh[t] = cell; }
        else        { mid_sh[15] = 3.0e38f; }
        int celln = __shfl_down_sync(0x0000ffffu, cell, 1);
        unsigned dup = __ballot_sync(0x0000ffffu, (t < 14) && (cell == celln));
        if (t == 0) flag_sh = (dup != 0u) ? 1 : 0;
    }

#pragma unroll
    for (int o = 16; o > 0; o >>= 1)
        ss += __shfl_xor_sync(0xffffffffu, ss, o);
    if ((t & 31) == 0) red[t >> 5] = ss;
    __syncthreads();                                   // barrier A

    // ---- LUT build: 4 cells/thread; tc via broadcast LDS (keeps regs low) ----
    {
        const int base = t * 4;
        int L0 = 0, L1 = 0, L2 = 0, L3 = 0;
#pragma unroll
        for (int j = 0; j < 15; j++) {
            int cj = tc_sh[j];
            L0 += (cj < base)     ? 1 : 0;
            L1 += (cj < base + 1) ? 1 : 0;
            L2 += (cj < base + 2) ? 1 : 0;
            L3 += (cj < base + 3) ? 1 : 0;
        }
        ((unsigned int*)lutL_sh)[t] =
            (unsigned)L0 | ((unsigned)L1 << 8) | ((unsigned)L2 << 16) | ((unsigned)L3 << 24);
        lutM_sh[base]     = mid_sh[L0];
        lutM_sh[base + 1] = mid_sh[L1];
        lutM_sh[base + 2] = mid_sh[L2];
        lutM_sh[base + 3] = mid_sh[L3];
    }

    if (t < (TPB / 32)) {
        float s2 = red[t];
#pragma unroll
        for (int o = (TPB / 64); o > 0; o >>= 1)
            s2 += __shfl_xor_sync((1u << (TPB / 32)) - 1u, s2, o);
        if (t == 0) norm_sh = fmaxf(sqrtf(s2), 1e-8f);
    }
    __syncthreads();                                   // barrier B

    const float norm = norm_sh;
    const float inv  = 1.0f / norm;
    const int   flag = flag_sh;

    const float4* rr = (const float4*)rot2;            // (c,s,c,s) per float4
    float4* xo = (float4*)(xhat  + (size_t)row * DIM);
    float4* io = (float4*)(idxout + (size_t)row * DIM);

    // ---- pass 2: re-read x from L1 (hits), transform, store ----
#pragma unroll
    for (int k = 0; k < VPT; k++) {
        const int j = t + k * TPB;
        const float4 xv = __ldcs(&xr[j]);              // L1 hit; demote after use
        const float4 rs = __ldg(&rr[j]);

        const float v0 = xv.x * inv, v1 = xv.y * inv;
        const float v2 = xv.z * inv, v3 = xv.w * inv;

        float r[4];
        r[0] = rs.x * v0 - rs.y * v1;
        r[1] = rs.y * v0 + rs.x * v1;
        r[2] = rs.z * v2 - rs.w * v3;
        r[3] = rs.w * v2 + rs.z * v3;

        float q[4], f[4];
        if (!flag) {
#pragma unroll
            for (int e = 0; e < 4; e++) {
                int cell = __float_as_int(fmaf(r[e], SCALEF, MAGICF)) - BITBASE;
                float midL = lutM_sh[cell];             // parallel with lutL load
                int   L    = (int)lutL_sh[cell];
                int   idx  = L + ((r[e] > midL) ? 1 : 0);  // strict >: ties->low idx
                q[e] = c_sh[idx];
                f[e] = (float)idx;
            }
        } else {
#pragma unroll
            for (int e = 0; e < 4; e++) {
                int idx = 0;
#pragma unroll
                for (int jj = 0; jj < 15; jj++) idx += (r[e] > mid_sh[jj]) ? 1 : 0;
                q[e] = c_sh[idx];
                f[e] = (float)idx;
            }
        }

        float4 out;
        out.x = (rs.x * q[0] + rs.y * q[1]) * norm;
        out.y = (rs.x * q[1] - rs.y * q[0]) * norm;
        out.z = (rs.z * q[2] + rs.w * q[3]) * norm;
        out.w = (rs.z * q[3] - rs.w * q[2]) * norm;
        __stcs(&xo[j], out);

        float4 fo;
        fo.x = f[0]; fo.y = f[1]; fo.z = f[2]; fo.w = f[3];
        __stcs(&io[j], fo);
    }
}

extern "C" void kernel_launch(void* const* d_in, const int* in_sizes, int n_in,
                              void* d_out, int out_size) {
    const float* x = nullptr;
    const float* cent = nullptr;
    const float* rot2 = nullptr;
    for (int i = 0; i < n_in; i++) {
        if (in_sizes[i] == ROWS * DIM) x    = (const float*)d_in[i];
        else if (in_sizes[i] == 16)    cent = (const float*)d_in[i];
        else if (in_sizes[i] == 4096)  rot2 = (const float*)d_in[i];
    }

    float* xhat = (float*)d_out;
    float* idxf = xhat + (long long)ROWS * DIM;

    pq_kernel<<<ROWS, TPB>>>(x, cent, rot2, xhat, idxf);
}